// round 8
// baseline (speedup 1.0000x reference)
#include <cuda_runtime.h>
#include <cstdint>

// LIF forward scan, 4 time steps. x/out: [4, N] fp32, N = 8,388,608.
// Forward value of the surrogate spike == hard threshold (mem > 0.5).
// HBM-bound streaming: 134 MiB read + 134 MiB write.
//
// R7: persistent grid-stride. Exactly 592 CTAs (148 SMs x 4 CTAs of 512
// threads = full occupancy in one wave); each thread loops over ~7 float4
// columns. Removes inter-wave CTA launch/drain and keeps LSU queues
// continuously fed. Loads stay evict-first (__ldcs), stores evict-first
// (__stcs) -- zero reuse in either direction.

static constexpr int STEP = 4;
static constexpr int GRID_CTAS = 148 * 4;   // one full wave at occ=4 (512 thr)
static constexpr int THREADS   = 512;

__device__ __forceinline__ void lif_step(float4& mem, const float4 xin, float4& s) {
    mem.x = fmaf(mem.x, 0.25f, xin.x); mem.y = fmaf(mem.y, 0.25f, xin.y);
    mem.z = fmaf(mem.z, 0.25f, xin.z); mem.w = fmaf(mem.w, 0.25f, xin.w);
    s.x = mem.x > 0.5f ? 1.f : 0.f;  s.y = mem.y > 0.5f ? 1.f : 0.f;
    s.z = mem.z > 0.5f ? 1.f : 0.f;  s.w = mem.w > 0.5f ? 1.f : 0.f;
    mem.x = s.x > 0.f ? 0.f : mem.x; mem.y = s.y > 0.f ? 0.f : mem.y;
    mem.z = s.z > 0.f ? 0.f : mem.z; mem.w = s.w > 0.f ? 0.f : mem.w;
}

__global__ __launch_bounds__(THREADS)
void lif_fwd_kernel(const float4* __restrict__ x, float4* __restrict__ out, int n4) {
    const int stride = GRID_CTAS * THREADS;

    for (int i = blockIdx.x * THREADS + threadIdx.x; i < n4; i += stride) {
        // 4 independent front-batched LDG.128 (one per time step), evict-first.
        float4 x0 = __ldcs(&x[0 * (size_t)n4 + i]);
        float4 x1 = __ldcs(&x[1 * (size_t)n4 + i]);
        float4 x2 = __ldcs(&x[2 * (size_t)n4 + i]);
        float4 x3 = __ldcs(&x[3 * (size_t)n4 + i]);

        float4 mem = make_float4(0.f, 0.f, 0.f, 0.f);
        float4 s;

        lif_step(mem, x0, s);
        __stcs(&out[0 * (size_t)n4 + i], s);

        lif_step(mem, x1, s);
        __stcs(&out[1 * (size_t)n4 + i], s);

        lif_step(mem, x2, s);
        __stcs(&out[2 * (size_t)n4 + i], s);

        lif_step(mem, x3, s);
        __stcs(&out[3 * (size_t)n4 + i], s);
    }
}

extern "C" void kernel_launch(void* const* d_in, const int* in_sizes, int n_in,
                              void* d_out, int out_size) {
    const float* x = (const float*)d_in[0];
    float* out = (float*)d_out;

    int total = in_sizes[0];          // STEP * N
    int n = total / STEP;             // 8,388,608 elements per step
    int n4 = n / 4;                   // 2,097,152 float4 per step

    lif_fwd_kernel<<<GRID_CTAS, THREADS>>>((const float4*)x, (float4*)out, n4);
}